// round 8
// baseline (speedup 1.0000x reference)
#include <cuda_runtime.h>
#include <cuda_bf16.h>

// Problem constants (fixed by setup_inputs)
#define L    4096
#define H    16
#define P    128
#define NS   256      // d_state
#define CH   256      // chunk
#define NC   16       // chunks per sequence
#define BD   4        // 2*b direction-batches (0,1 fwd ; 2,3 bwd)
#define DIN  2048

typedef unsigned long long u64t;

// packed f32x2 FMA: d = a*b + d (elementwise on 2 packed floats)
__device__ __forceinline__ void ffma2(u64t &d, u64t a, u64t b) {
    asm("fma.rn.f32x2 %0, %1, %2, %0;" : "+l"(d) : "l"(a), "l"(b));
}
__device__ __forceinline__ float2 unpk2(u64t v) {
    float2 f; asm("mov.b64 {%0,%1}, %2;" : "=f"(f.x), "=f"(f.y) : "l"(v)); return f;
}

// ---------------- scratch (static device globals; no runtime allocation) ----
__device__ __align__(16) float g_dtw[BD * L * H];                 // softplus(dt), flipped layout
__device__ __align__(16) float g_cs [BD * L * H];                 // per-chunk inclusive cumsum of dt*A
__device__ __align__(16) float g_CB [BD * NC * CH * CH];          // C @ B^T per chunk (67MB)
__device__ __align__(16) float g_y  [(size_t)BD * L * DIN];       // y_intra + y_inter (134MB)
__device__ __align__(16) float g_st [(size_t)BD * NC * H * NS * P]; // states -> prev (134MB)

// ---------------------------------------------------------------------------
// K1: softplus(dt) and per-chunk cumsum of dA = dt*A, in flipped (bd) layout.
// ---------------------------------------------------------------------------
__global__ void k_prep(const float* __restrict__ dt, const float* __restrict__ A_log)
{
    int j  = blockIdx.x;
    int bd = blockIdx.y;
    int i  = threadIdx.x;
    bool rev = (bd >= 2);
    int bb = rev ? bd - 2 : bd;
    int t  = j * CH + i;
    int to = rev ? (L - 1 - t) : t;
    __shared__ float s[CH];

    for (int h = 0; h < H; h++) {
        int col = rev ? (H + h) : h;
        float v  = dt[(size_t)(bb * L + to) * (2 * H) + col];
        float sp = fmaxf(v, 0.f) + log1pf(expf(-fabsf(v)));
        g_dtw[(size_t)(bd * L + t) * H + h] = sp;
        float a  = -expf(A_log[h]);
        float dA = sp * a;
        s[i] = dA;
        __syncthreads();
        #pragma unroll
        for (int off = 1; off < CH; off <<= 1) {
            float add = (i >= off) ? s[i - off] : 0.f;
            __syncthreads();
            s[i] += add;
            __syncthreads();
        }
        g_cs[(size_t)(bd * L + t) * H + h] = s[i];
        __syncthreads();
    }
}

// ---------------------------------------------------------------------------
// K2: CB[bd,j,i,k] = sum_n C[i,n] * B[k,n]   (unchanged — known good)
// ---------------------------------------------------------------------------
__global__ void k_cb(const float* __restrict__ BC)
{
    int ti = blockIdx.x, tk = blockIdx.y;
    int bd = blockIdx.z >> 4, j = blockIdx.z & 15;
    bool rev = (bd >= 2); int bb = rev ? bd - 2 : bd;
    int tbase = j * CH;

    __shared__ float Cs[64][33];
    __shared__ float Bs[64][33];

    int tid = threadIdx.x;
    int ty = tid >> 4, tx = tid & 15;
    float acc[4][4];
    #pragma unroll
    for (int a = 0; a < 4; a++)
        #pragma unroll
        for (int b = 0; b < 4; b++) acc[a][b] = 0.f;

    for (int n0 = 0; n0 < NS; n0 += 32) {
        #pragma unroll
        for (int r = 0; r < 8; r++) {
            int e = tid + 256 * r;
            int row = e >> 5, col = e & 31;
            int tC = tbase + ti * 64 + row; int toC = rev ? (L - 1 - tC) : tC;
            Cs[row][col] = BC[(size_t)(bb * L + toC) * (2 * NS) + NS + n0 + col];
            int tB = tbase + tk * 64 + row; int toB = rev ? (L - 1 - tB) : tB;
            Bs[row][col] = BC[(size_t)(bb * L + toB) * (2 * NS) + n0 + col];
        }
        __syncthreads();
        #pragma unroll 8
        for (int n = 0; n < 32; n++) {
            float cv[4], bv[4];
            #pragma unroll
            for (int a = 0; a < 4; a++) cv[a] = Cs[ty * 4 + a][n];
            #pragma unroll
            for (int b = 0; b < 4; b++) bv[b] = Bs[tx * 4 + b][n];
            #pragma unroll
            for (int a = 0; a < 4; a++)
                #pragma unroll
                for (int b = 0; b < 4; b++) acc[a][b] += cv[a] * bv[b];
        }
        __syncthreads();
    }
    #pragma unroll
    for (int a = 0; a < 4; a++)
        #pragma unroll
        for (int b = 0; b < 4; b++)
            g_CB[((size_t)(bd * NC + j) * CH + ti * 64 + ty * 4 + a) * CH + tk * 64 + tx * 4 + b] = acc[a][b];
}

// ---------------------------------------------------------------------------
// K3: y_intra[i,p] = sum_{k<=i} CB[i,k] exp(cs_i - cs_k) dt_k x[k,p]
// f32x2 inner loop; G stored pre-duplicated as float2; k-subtile = 32
// grid (4 i-tiles, H, 64 bd*j), 256 threads
// ---------------------------------------------------------------------------
__global__ void __launch_bounds__(256) k_yintra(const float* __restrict__ x)
{
    int it = blockIdx.x;
    int h  = blockIdx.y;
    int bd = blockIdx.z >> 4, j = blockIdx.z & 15;
    bool rev = (bd >= 2); int bb = rev ? bd - 2 : bd;
    int tbase = j * CH;
    int tid = threadIdx.x;

    __shared__ __align__(16) float Xs[32 * 128];   // [k][p]
    __shared__ __align__(16) u64t  Gs2[64 * 34];   // [i][k] dup float2, pad 34
    __shared__ float csi_s[64];

    int ty = tid >> 5, tx = tid & 31;
    u64t acc[8][2];
    #pragma unroll
    for (int r = 0; r < 8; r++) { acc[r][0] = 0ull; acc[r][1] = 0ull; }

    const float* csb = g_cs  + (size_t)(bd * L + tbase) * H + h;
    const float* dtb = g_dtw + (size_t)(bd * L + tbase) * H + h;
    const float* cbb = g_CB + (size_t)(bd * NC + j) * CH * CH;

    if (tid < 64) csi_s[tid] = csb[(it * 64 + tid) * H];
    __syncthreads();

    int kloc = tid & 31;
    int igrp = tid >> 5;

    int ktmax = 2 * it + 1;
    for (int kt = 0; kt <= ktmax; kt++) {
        // X subtile: 32k x 128p
        #pragma unroll
        for (int r = 0; r < 4; r++) {
            int e4 = tid + 256 * r;
            int k = e4 >> 5, p4 = e4 & 31;
            int tt = tbase + kt * 32 + k;
            int to = rev ? (L - 1 - tt) : tt;
            reinterpret_cast<float4*>(Xs)[e4] =
                reinterpret_cast<const float4*>(x + (size_t)(bb * L + to) * DIN + h * P)[p4];
        }
        // G subtile (duplicated)
        {
            int kk = kt * 32 + kloc;
            float csk = csb[kk * H];
            float dtk = dtb[kk * H];
            #pragma unroll
            for (int q = 0; q < 8; q++) {
                int iloc = igrp * 8 + q;
                int ii = it * 64 + iloc;
                float g = 0.f;
                if (kk <= ii)
                    g = cbb[(size_t)ii * CH + kk] * __expf(csi_s[iloc] - csk) * dtk;
                *reinterpret_cast<float2*>(&Gs2[iloc * 34 + kloc]) = make_float2(g, g);
            }
        }
        __syncthreads();
        #pragma unroll 4
        for (int k = 0; k < 32; k += 2) {
            ulonglong2 xv0 = *reinterpret_cast<const ulonglong2*>(Xs + k * 128 + tx * 4);
            ulonglong2 xv1 = *reinterpret_cast<const ulonglong2*>(Xs + (k + 1) * 128 + tx * 4);
            #pragma unroll
            for (int r = 0; r < 8; r++) {
                ulonglong2 g2 = *reinterpret_cast<const ulonglong2*>(&Gs2[(ty * 8 + r) * 34 + k]);
                ffma2(acc[r][0], g2.x, xv0.x);
                ffma2(acc[r][1], g2.x, xv0.y);
                ffma2(acc[r][0], g2.y, xv1.x);
                ffma2(acc[r][1], g2.y, xv1.y);
            }
        }
        __syncthreads();
    }
    #pragma unroll
    for (int r = 0; r < 8; r++) {
        int ii = it * 64 + ty * 8 + r;
        float2 a0 = unpk2(acc[r][0]);
        float2 a1 = unpk2(acc[r][1]);
        float4 o = make_float4(a0.x, a0.y, a1.x, a1.y);
        reinterpret_cast<float4*>(g_y + (size_t)(bd * L + tbase + ii) * DIN + h * P)[tx] = o;
    }
}

// ---------------------------------------------------------------------------
// K4: states[n,p] = sum_k (w_k B[k,n]) x[k,p],  w_k = exp(cs_last - cs_k) dt_k
// f32x2 inner loop; w folded into duplicated B tile; k-subtile = 32
// grid (4 n-tiles, H, 64 bd*j)
// ---------------------------------------------------------------------------
__global__ void __launch_bounds__(256) k_states(const float* __restrict__ x,
                                                const float* __restrict__ BC)
{
    int nt = blockIdx.x;
    int h  = blockIdx.y;
    int bd = blockIdx.z >> 4, j = blockIdx.z & 15;
    bool rev = (bd >= 2); int bb = rev ? bd - 2 : bd;
    int tbase = j * CH;
    int tid = threadIdx.x;

    __shared__ float ws[CH];
    __shared__ __align__(16) float Xs[32 * 128];  // [k][p]
    __shared__ __align__(16) u64t  Bs2[32 * 64];  // [k][n] dup float2, w folded

    int ty = tid >> 5, tx = tid & 31;
    u64t acc[8][2];
    #pragma unroll
    for (int r = 0; r < 8; r++) { acc[r][0] = 0ull; acc[r][1] = 0ull; }

    const float* csb = g_cs  + (size_t)(bd * L + tbase) * H + h;
    const float* dtb = g_dtw + (size_t)(bd * L + tbase) * H + h;
    {
        float cslast = csb[255 * H];
        ws[tid] = __expf(cslast - csb[tid * H]) * dtb[tid * H];
    }
    __syncthreads();

    for (int kt = 0; kt < 8; kt++) {
        #pragma unroll
        for (int r = 0; r < 4; r++) {
            int e4 = tid + 256 * r;
            int k = e4 >> 5, p4 = e4 & 31;
            int tt = tbase + kt * 32 + k;
            int to = rev ? (L - 1 - tt) : tt;
            reinterpret_cast<float4*>(Xs)[e4] =
                reinterpret_cast<const float4*>(x + (size_t)(bb * L + to) * DIN + h * P)[p4];
        }
        #pragma unroll
        for (int r = 0; r < 2; r++) {
            int e = tid + 256 * r;
            int k = e >> 4, n4 = e & 15;
            int tt = tbase + kt * 32 + k;
            int to = rev ? (L - 1 - tt) : tt;
            float w = ws[kt * 32 + k];
            float4 v = reinterpret_cast<const float4*>(BC + (size_t)(bb * L + to) * (2 * NS))[nt * 16 + n4];
            float4* dst = reinterpret_cast<float4*>(&Bs2[k * 64 + n4 * 4]);
            dst[0] = make_float4(v.x * w, v.x * w, v.y * w, v.y * w);
            dst[1] = make_float4(v.z * w, v.z * w, v.w * w, v.w * w);
        }
        __syncthreads();
        #pragma unroll 4
        for (int k = 0; k < 32; k++) {
            ulonglong2 xv = *reinterpret_cast<const ulonglong2*>(Xs + k * 128 + tx * 4);
            const u64t* cb = &Bs2[k * 64 + ty * 8];
            ulonglong2 c01 = *reinterpret_cast<const ulonglong2*>(cb);
            ulonglong2 c23 = *reinterpret_cast<const ulonglong2*>(cb + 2);
            ulonglong2 c45 = *reinterpret_cast<const ulonglong2*>(cb + 4);
            ulonglong2 c67 = *reinterpret_cast<const ulonglong2*>(cb + 6);
            ffma2(acc[0][0], c01.x, xv.x); ffma2(acc[0][1], c01.x, xv.y);
            ffma2(acc[1][0], c01.y, xv.x); ffma2(acc[1][1], c01.y, xv.y);
            ffma2(acc[2][0], c23.x, xv.x); ffma2(acc[2][1], c23.x, xv.y);
            ffma2(acc[3][0], c23.y, xv.x); ffma2(acc[3][1], c23.y, xv.y);
            ffma2(acc[4][0], c45.x, xv.x); ffma2(acc[4][1], c45.x, xv.y);
            ffma2(acc[5][0], c45.y, xv.x); ffma2(acc[5][1], c45.y, xv.y);
            ffma2(acc[6][0], c67.x, xv.x); ffma2(acc[6][1], c67.x, xv.y);
            ffma2(acc[7][0], c67.y, xv.x); ffma2(acc[7][1], c67.y, xv.y);
        }
        __syncthreads();
    }
    #pragma unroll
    for (int r = 0; r < 8; r++) {
        int n = nt * 64 + ty * 8 + r;
        float2 a0 = unpk2(acc[r][0]);
        float2 a1 = unpk2(acc[r][1]);
        float4 o = make_float4(a0.x, a0.y, a1.x, a1.y);
        reinterpret_cast<float4*>(g_st)[(((size_t)(bd * NC + j) * H + h) * NS + n) * 32 + tx] = o;
    }
}

// ---------------------------------------------------------------------------
// K5: sequential inter-chunk scan (in-place: states -> prev-at-chunk-start)
// ---------------------------------------------------------------------------
__global__ void k_scan()
{
    int g = blockIdx.x * 256 + threadIdx.x;
    int bd = g >> 19;
    int inner = g & ((1 << 19) - 1);
    int h = inner >> 15;
    const float* csb = g_cs + (size_t)(bd * L) * H + h;
    float* base = g_st + ((size_t)bd << 23) + inner;
    float carry = 0.f;
    #pragma unroll
    for (int j = 0; j < NC; j++) {
        float s = base[(size_t)j << 19];
        base[(size_t)j << 19] = carry;
        float cd = __expf(csb[(j * CH + 255) * H]);
        carry = carry * cd + s;
    }
}

// ---------------------------------------------------------------------------
// K6: y_inter[i,p] = exp(cs_i) * sum_n C[i,n] prev[n,p]   (adds into g_y)
// f32x2 inner loop; C stored transposed+duplicated [n][i]; n-subtile = 32
// grid (4 i-tiles, H, 64 bd*j)
// ---------------------------------------------------------------------------
__global__ void __launch_bounds__(256) k_yinter(const float* __restrict__ BC)
{
    int it = blockIdx.x;
    int h  = blockIdx.y;
    int bd = blockIdx.z >> 4, j = blockIdx.z & 15;
    bool rev = (bd >= 2); int bb = rev ? bd - 2 : bd;
    int tbase = j * CH;
    int tid = threadIdx.x;

    __shared__ __align__(16) float Ps[32 * 128];  // [n][p] prev subtile
    __shared__ __align__(16) u64t  Cs2[32 * 66];  // [n][i] dup float2, pad 66

    int ty = tid >> 5, tx = tid & 31;
    u64t acc[8][2];
    #pragma unroll
    for (int r = 0; r < 8; r++) { acc[r][0] = 0ull; acc[r][1] = 0ull; }

    const float* stb = g_st + (((size_t)(bd * NC + j)) * H + h) * NS * P;

    for (int nt2 = 0; nt2 < 8; nt2++) {
        #pragma unroll
        for (int r = 0; r < 4; r++) {
            int e4 = tid + 256 * r;
            int nn = e4 >> 5, p4 = e4 & 31;
            reinterpret_cast<float4*>(Ps)[e4] =
                reinterpret_cast<const float4*>(stb + (size_t)(nt2 * 32 + nn) * P)[p4];
        }
        #pragma unroll
        for (int r = 0; r < 2; r++) {
            int e = tid + 256 * r;
            int i = e >> 3, n4 = e & 7;
            int tt = tbase + it * 64 + i;
            int to = rev ? (L - 1 - tt) : tt;
            float4 c = reinterpret_cast<const float4*>(BC + (size_t)(bb * L + to) * (2 * NS) + NS)[nt2 * 8 + n4];
            *reinterpret_cast<float2*>(&Cs2[(n4 * 4 + 0) * 66 + i]) = make_float2(c.x, c.x);
            *reinterpret_cast<float2*>(&Cs2[(n4 * 4 + 1) * 66 + i]) = make_float2(c.y, c.y);
            *reinterpret_cast<float2*>(&Cs2[(n4 * 4 + 2) * 66 + i]) = make_float2(c.z, c.z);
            *reinterpret_cast<float2*>(&Cs2[(n4 * 4 + 3) * 66 + i]) = make_float2(c.w, c.w);
        }
        __syncthreads();
        #pragma unroll 4
        for (int n = 0; n < 32; n++) {
            ulonglong2 xv = *reinterpret_cast<const ulonglong2*>(Ps + n * 128 + tx * 4);
            const u64t* cb = &Cs2[n * 66 + ty * 8];
            ulonglong2 c01 = *reinterpret_cast<const ulonglong2*>(cb);
            ulonglong2 c23 = *reinterpret_cast<const ulonglong2*>(cb + 2);
            ulonglong2 c45 = *reinterpret_cast<const ulonglong2*>(cb + 4);
            ulonglong2 c67 = *reinterpret_cast<const ulonglong2*>(cb + 6);
            ffma2(acc[0][0], c01.x, xv.x); ffma2(acc[0][1], c01.x, xv.y);
            ffma2(acc[1][0], c01.y, xv.x); ffma2(acc[1][1], c01.y, xv.y);
            ffma2(acc[2][0], c23.x, xv.x); ffma2(acc[2][1], c23.x, xv.y);
            ffma2(acc[3][0], c23.y, xv.x); ffma2(acc[3][1], c23.y, xv.y);
            ffma2(acc[4][0], c45.x, xv.x); ffma2(acc[4][1], c45.x, xv.y);
            ffma2(acc[5][0], c45.y, xv.x); ffma2(acc[5][1], c45.y, xv.y);
            ffma2(acc[6][0], c67.x, xv.x); ffma2(acc[6][1], c67.x, xv.y);
            ffma2(acc[7][0], c67.y, xv.x); ffma2(acc[7][1], c67.y, xv.y);
        }
        __syncthreads();
    }
    const float* csb = g_cs + (size_t)(bd * L + tbase) * H + h;
    #pragma unroll
    for (int r = 0; r < 8; r++) {
        int ii = it * 64 + ty * 8 + r;
        float e = __expf(csb[ii * H]);
        float2 a0 = unpk2(acc[r][0]);
        float2 a1 = unpk2(acc[r][1]);
        float4* yp = reinterpret_cast<float4*>(g_y + (size_t)(bd * L + tbase + ii) * DIN + h * P) + tx;
        float4 v = *yp;
        v.x += e * a0.x; v.y += e * a0.y;
        v.z += e * a1.x; v.w += e * a1.y;
        *yp = v;
    }
}

// ---------------------------------------------------------------------------
// K7: gate = x @ W^T + D; out = roll(y_fw) + flip(roll(y_bw)) + x*repeat(gate)
// ---------------------------------------------------------------------------
__global__ void k_final(const float* __restrict__ x, const float* __restrict__ W,
                        const float* __restrict__ Dv, float* __restrict__ out)
{
    int blk = blockIdx.x;
    int bb = blk >> 10;
    int t0 = (blk & 1023) * 4;
    int tid = threadIdx.x;

    __shared__ __align__(16) float xs[4 * DIN];
    __shared__ float gates[4][H];

    #pragma unroll
    for (int r = 0; r < 8; r++) {
        int e4 = tid + 256 * r;
        int tt = e4 >> 9, d4 = e4 & 511;
        reinterpret_cast<float4*>(xs)[e4] =
            reinterpret_cast<const float4*>(x + (size_t)(bb * L + t0 + tt) * DIN)[d4];
    }
    __syncthreads();

    int w = tid >> 5, lane = tid & 31;
    #pragma unroll
    for (int e = 0; e < 2; e++) {
        int hh = w * 2 + e;
        float p0 = 0.f, p1 = 0.f, p2 = 0.f, p3 = 0.f;
        for (int d = lane; d < DIN; d += 32) {
            float wv = W[(size_t)hh * DIN + d];
            p0 += xs[0 * DIN + d] * wv;
            p1 += xs[1 * DIN + d] * wv;
            p2 += xs[2 * DIN + d] * wv;
            p3 += xs[3 * DIN + d] * wv;
        }
        #pragma unroll
        for (int off = 16; off > 0; off >>= 1) {
            p0 += __shfl_xor_sync(0xffffffffu, p0, off);
            p1 += __shfl_xor_sync(0xffffffffu, p1, off);
            p2 += __shfl_xor_sync(0xffffffffu, p2, off);
            p3 += __shfl_xor_sync(0xffffffffu, p3, off);
        }
        if (lane == 0) {
            float dd = Dv[hh];
            gates[0][hh] = p0 + dd; gates[1][hh] = p1 + dd;
            gates[2][hh] = p2 + dd; gates[3][hh] = p3 + dd;
        }
    }
    __syncthreads();

    #pragma unroll
    for (int r = 0; r < 8; r++) {
        int e4 = tid + 256 * r;
        int tt = e4 >> 9, d4 = e4 & 511;
        int t = t0 + tt;
        int d = d4 * 4, h = d >> 7;
        float4 yf = make_float4(0.f, 0.f, 0.f, 0.f);
        float4 yb = make_float4(0.f, 0.f, 0.f, 0.f);
        if (t > 0)
            yf = reinterpret_cast<const float4*>(g_y + (size_t)(bb * L + t - 1) * DIN)[d4];
        if (t < L - 1)
            yb = reinterpret_cast<const float4*>(g_y + (size_t)((2 + bb) * L + (L - 2 - t)) * DIN)[d4];
        float gt = gates[tt][h];
        float4 xv = reinterpret_cast<const float4*>(xs)[e4];
        float4 o;
        o.x = yf.x + yb.x + xv.x * gt;
        o.y = yf.y + yb.y + xv.y * gt;
        o.z = yf.z + yb.z + xv.z * gt;
        o.w = yf.w + yb.w + xv.w * gt;
        reinterpret_cast<float4*>(out + (size_t)(bb * L + t) * DIN)[d4] = o;
    }
}

// ---------------------------------------------------------------------------
extern "C" void kernel_launch(void* const* d_in, const int* in_sizes, int n_in,
                              void* d_out, int out_size)
{
    const float* x     = (const float*)d_in[0];   // (2,4096,2048)
    const float* BC    = (const float*)d_in[1];   // (2,4096,512)
    const float* dt    = (const float*)d_in[2];   // (2,4096,32)
    const float* A_log = (const float*)d_in[3];   // (16,)
    const float* Dv    = (const float*)d_in[4];   // (16,)
    const float* W     = (const float*)d_in[5];   // (16,2048)
    float* out = (float*)d_out;

    k_prep  <<<dim3(NC, BD),     256>>>(dt, A_log);
    k_cb    <<<dim3(4, 4, 64),   256>>>(BC);
    k_yintra<<<dim3(4, H, 64),   256>>>(x);
    k_states<<<dim3(4, H, 64),   256>>>(x, BC);
    k_scan  <<<8192,             256>>>();
    k_yinter<<<dim3(4, H, 64),   256>>>(BC);
    k_final <<<2048,             256>>>(x, W, Dv, out);
}